// round 15
// baseline (speedup 1.0000x reference)
#include <cuda_runtime.h>
#include <cuda_bf16.h>

#define HH 1024
#define WW 1024
#define BB 16
#define PCOUNT (1024*1024)
#define PSTRIDE (2*PCOUNT)
#define NOCT 3              // octaves 3..7 weigh <=2^-15 -> ~1e-5 rel error
#define NCHUNK 4
#define IMG_PER_CHUNK (BB / NCHUNK)

// Per-octave compact windows (right-sized): o0 14x16, o1 24x32, o2 46x64
#define O0_OFF   0
#define O0_STR   16
#define O0_CNT   (14*16)
#define O1_OFF   O0_CNT
#define O1_STR   32
#define O1_CNT   (24*32)
#define O2_OFF   (O0_CNT+O1_CNT)
#define O2_STR   64
#define O2_CNT   (46*64)
#define IMG_TAB  (O0_CNT+O1_CNT+O2_CNT)   // 3936 float4 = 63 KB per image

__device__ float4 g_ctab[BB * IMG_TAB];   // ~1 MB (L2-resident)
__device__ float  g_acc[BB * HH * WW];    // 64 MB accumulator (L2-resident)
__device__ int    g_mn[BB], g_mx[BB];

__device__ __forceinline__ int fenc(float f) {
    int i = __float_as_int(f);
    return i >= 0 ? i : (i ^ 0x7fffffff);
}
__device__ __forceinline__ float fdec(int i) {
    return __int_as_float(i >= 0 ? i : (i ^ 0x7fffffff));
}
__device__ __forceinline__ float fade_f(float t) {
    return ((t * t) * t) * (t * (t * 6.0f - 15.0f) + 10.0f);
}
__device__ __forceinline__ void gcoef(int h, float& cx, float& cy, float& cz) {
    float s1 = (h & 1) ? -1.0f : 1.0f;
    float s2 = (h & 2) ? -1.0f : 1.0f;
    bool hx = h < 8;
    bool vy = h < 4;
    bool vx = ((h | 2) == 14);
    cx = (hx ? s1 : 0.0f) + (vx ? s2 : 0.0f);
    cy = (hx ? 0.0f : s1) + (vy ? s2 : 0.0f);
    cz = (!vy && !vx) ? s2 : 0.0f;
}

// Right-sized tables: one entry per thread. grid = (BB, 16) x 256 threads.
__global__ void __launch_bounds__(256) k_tables(const int* __restrict__ p_all,
                                                const float* __restrict__ Xp,
                                                const float* __restrict__ Yp,
                                                const float* __restrict__ Zp) {
    int b = blockIdx.x;
    int t = blockIdx.y * 256 + threadIdx.x;

    if (blockIdx.x == 0 && blockIdx.y == 0 && threadIdx.x < BB) {
        g_mn[threadIdx.x] = 0x7fffffff;
        g_mx[threadIdx.x] = (int)0x80000000;
    }
    if (t >= IMG_TAB) return;

    int o, ix, iy;
    if (t < O1_OFF)      { o = 0; int r = t;          iy = r >> 4; ix = r & 15; }
    else if (t < O2_OFF) { o = 1; int r = t - O1_OFF; iy = r >> 5; ix = r & 31; }
    else                 { o = 2; int r = t - O2_OFF; iy = r >> 6; ix = r & 63; }

    const int* __restrict__ p = p_all + (size_t)b * PSTRIDE;
    float fr = (float)(1 << o);
    int basex = (int)floorf(__fdiv_rn(Xp[0], 100.0f) * fr);
    int basey = (int)floorf(__fdiv_rn(Yp[0], 100.0f) * fr);

    float fz = __fdiv_rn(0.1f * (float)b + Zp[0], 100.0f) * fr;
    float flz = floorf(fz);
    float zf = fz - flz;
    float zm = zf - 1.0f;
    float w  = fade_f(zf);
    int Zi = ((int)flz) % 255;

    int Xi = (basex + ix) % 255;
    int Yi = (basey + iy) % 255;
    int pXi = __ldg(&p[Xi]);
    int A   = __ldg(&p[pXi + Yi]);
    int tt  = A + Zi;
    int h0  = __ldg(&p[tt]) & 15;
    int h1  = __ldg(&p[tt + 1]) & 15;

    float cx0, cy0, cz0, cx1, cy1, cz1;
    gcoef(h0, cx0, cy0, cz0);
    gcoef(h1, cx1, cy1, cz1);
    float bxc = fmaf(w, cx1 - cx0, cx0);
    float byc = fmaf(w, cy1 - cy0, cy0);
    float t0 = cz0 * zf;
    float a  = fmaf(w, fmaf(cz1, zm, -t0), t0);
    g_ctab[(size_t)b * IMG_TAB + t] = make_float4(a, bxc, byc, 0.0f);
}

// Noise: warp = 32 cols x 8 rows; block = 32 cols x 64 rows. 3 octaves, factorized.
// grid = (32, 16, IMG_PER_CHUNK); image = b0 + blockIdx.z.
__global__ void __launch_bounds__(256) k_noise(const float* __restrict__ Xp,
                                               const float* __restrict__ Yp,
                                               int b0) {
    int b = b0 + blockIdx.z;
    int lane = threadIdx.x & 31;
    int wid = threadIdx.x >> 5;
    int col = blockIdx.x * 32 + lane;
    int row0 = blockIdx.y * 64;

    const int STRS[NOCT] = {O0_STR, O1_STR, O2_STR};

    __shared__ float4 sy[NOCT][64];   // (yf, ym, v, packed offset OFF[o]+iy*STR[o])
    if (threadIdx.x < NOCT * 64) {
        int o = threadIdx.x >> 6;
        int i = threadIdx.x & 63;
        float fr = (float)(1 << o);
        int basey = (int)floorf(__fdiv_rn(Yp[0], 100.0f) * fr);
        float fy = __fdiv_rn((float)(row0 + i) + Yp[0], 100.0f) * fr;
        float fly = floorf(fy);
        float yf = fy - fly;
        int iy = (int)fly - basey;
        int str = (o == 0) ? O0_STR : (o == 1) ? O1_STR : O2_STR;
        int ofs = (o == 0) ? O0_OFF : (o == 1) ? O1_OFF : O2_OFF;
        sy[o][i] = make_float4(yf, yf - 1.0f, fade_f(yf),
                               __int_as_float(ofs + iy * str));
    }
    __syncthreads();

    float bXf = __fdiv_rn(Xp[0], 100.0f);
    float bx = __fdiv_rn((float)col + Xp[0], 100.0f);
    const float4* __restrict__ tbI = g_ctab + (size_t)b * IMG_TAB;

    float acc[8] = {0.f, 0.f, 0.f, 0.f, 0.f, 0.f, 0.f, 0.f};
    float freq = 1.0f;
    float camp = 1.0f;
#pragma unroll
    for (int o = 0; o < NOCT; o++) {
        const int STR = STRS[o];
        float fx = bx * freq;
        float flx = floorf(fx);
        float xf = fx - flx;
        int ix = (int)flx - (int)floorf(bXf * freq);
        float u = fade_f(xf);
        float xm = xf - 1.0f;

        float4 yd[8];
#pragma unroll
        for (int r = 0; r < 8; r++) yd[r] = sy[o][wid * 8 + r];
        int k0 = __float_as_int(yd[0].w);
        int k7 = __float_as_int(yd[7].w);

        const float4* __restrict__ rpA = tbI + k0 + ix;
        float4 a00 = rpA[0], a10 = rpA[1], a01 = rpA[STR], a11 = rpA[STR + 1];
        float A0 = fmaf(a00.y, xf, a00.x);
        float A1 = fmaf(a10.y, xm, a10.x);
        float A2 = fmaf(a01.y, xf, a01.x);
        float A3 = fmaf(a11.y, xm, a11.x);
        float P0A = fmaf(u, A1 - A0, A0);
        float Q0A = fmaf(u, a10.z - a00.z, a00.z);
        float P1A = fmaf(u, A3 - A2, A2);
        float Q1A = fmaf(u, a11.z - a01.z, a01.z);

        if (k0 == k7) {  // all 8 rows in one lattice row (warp-uniform branch)
#pragma unroll
            for (int r = 0; r < 8; r++) {
                float nx0 = fmaf(Q0A, yd[r].x, P0A);
                float nx1 = fmaf(Q1A, yd[r].y, P1A);
                float n   = fmaf(yd[r].z, nx1 - nx0, nx0);
                acc[r] = fmaf(n, camp, acc[r]);
            }
        } else {         // straddles exactly 2 lattice rows
            const float4* __restrict__ rpB = tbI + k7 + ix;
            float4 b00 = rpB[0], b10 = rpB[1], b01 = rpB[STR], b11 = rpB[STR + 1];
            float B0 = fmaf(b00.y, xf, b00.x);
            float B1 = fmaf(b10.y, xm, b10.x);
            float B2 = fmaf(b01.y, xf, b01.x);
            float B3 = fmaf(b11.y, xm, b11.x);
            float P0B = fmaf(u, B1 - B0, B0);
            float Q0B = fmaf(u, b10.z - b00.z, b00.z);
            float P1B = fmaf(u, B3 - B2, B2);
            float Q1B = fmaf(u, b11.z - b01.z, b01.z);
#pragma unroll
            for (int r = 0; r < 8; r++) {
                bool lo = (__float_as_int(yd[r].w) == k0);
                float P0 = lo ? P0A : P0B;
                float Q0 = lo ? Q0A : Q0B;
                float P1 = lo ? P1A : P1B;
                float Q1 = lo ? Q1A : Q1B;
                float nx0 = fmaf(Q0, yd[r].x, P0);
                float nx1 = fmaf(Q1, yd[r].y, P1);
                float n   = fmaf(yd[r].z, nx1 - nx0, nx0);
                acc[r] = fmaf(n, camp, acc[r]);
            }
        }
        freq *= 2.0f;
        camp *= 0.03125f;
    }

    size_t pbase = ((size_t)b << 20) + (size_t)(row0 + wid * 8) * WW + col;
#pragma unroll
    for (int r = 0; r < 8; r++) g_acc[pbase + (size_t)r * WW] = acc[r];

    float amn = acc[0], amx = acc[0];
#pragma unroll
    for (int r = 1; r < 8; r++) { amn = fminf(amn, acc[r]); amx = fmaxf(amx, acc[r]); }
    int mn = fenc(amn), mx = fenc(amx);
#pragma unroll
    for (int s = 16; s; s >>= 1) {
        mn = min(mn, __shfl_xor_sync(0xffffffffu, mn, s));
        mx = max(mx, __shfl_xor_sync(0xffffffffu, mx, s));
    }
    __shared__ int smn[8], smx[8];
    if (lane == 0) { smn[wid] = mn; smx[wid] = mx; }
    __syncthreads();
    if (threadIdx.x == 0) {
#pragma unroll
        for (int i = 1; i < 8; i++) { mn = min(mn, smn[i]); mx = max(mx, smx[i]); }
        atomicMin(&g_mn[b], mn);
        atomicMax(&g_mx[b], mx);
    }
}

// Normalize chunk: grid = (512, IMG_PER_CHUNK); image = b0 + blockIdx.y.
__global__ void __launch_bounds__(256) k_norm(float* __restrict__ out, int b0) {
    int b = b0 + blockIdx.y;
    float mn = fdec(g_mn[b]);
    float mx = fdec(g_mx[b]);
    float inv = 1.0f / (mx - mn);
    const float4* __restrict__ src = reinterpret_cast<const float4*>(g_acc) + ((size_t)b << 18);
    float4* __restrict__ dst = reinterpret_cast<float4*>(out) + ((size_t)b << 18);
#pragma unroll
    for (int j = 0; j < 2; j++) {
        int idx = blockIdx.x * 512 + j * 256 + threadIdx.x;
        float4 a = __ldcs(&src[idx]);
        a.x = (a.x - mn) * inv;
        a.y = (a.y - mn) * inv;
        a.z = (a.z - mn) * inv;
        a.w = (a.w - mn) * inv;
        __stcs(&dst[idx], a);
    }
}

extern "C" void kernel_launch(void* const* d_in, const int* in_sizes, int n_in,
                              void* d_out, int out_size) {
    const int* p_all  = (const int*)d_in[0];
    const float* X    = (const float*)d_in[1];
    const float* Y    = (const float*)d_in[2];
    const float* Z    = (const float*)d_in[3];
    float* out        = (float*)d_out;

    // Lazily create side stream + events ONCE, on the first (uncaptured)
    // correctness call. Reused on the capture call — no creation inside capture.
    static cudaStream_t s2 = nullptr;
    static cudaEvent_t evn[NCHUNK], evj;
    if (s2 == nullptr) {
        cudaStreamCreateWithFlags(&s2, cudaStreamNonBlocking);
        for (int c = 0; c < NCHUNK; c++)
            cudaEventCreateWithFlags(&evn[c], cudaEventDisableTiming);
        cudaEventCreateWithFlags(&evj, cudaEventDisableTiming);
    }

    dim3 gt(BB, 16);
    k_tables<<<gt, 256>>>(p_all, X, Y, Z);

    dim3 gn(WW / 32, HH / 64, IMG_PER_CHUNK);
    dim3 gz(512, IMG_PER_CHUNK);
    for (int c = 0; c < NCHUNK; c++) {
        int b0 = c * IMG_PER_CHUNK;
        k_noise<<<gn, 256>>>(X, Y, b0);                 // main stream
        cudaEventRecord(evn[c], 0);
        cudaStreamWaitEvent(s2, evn[c], 0);
        k_norm<<<gz, 256, 0, s2>>>(out, b0);            // side stream, overlapped
    }
    cudaEventRecord(evj, s2);
    cudaStreamWaitEvent(0, evj, 0);                     // join before capture ends
}

// round 16
// speedup vs baseline: 1.2475x; 1.2475x over previous
#include <cuda_runtime.h>
#include <cuda_bf16.h>

#define HH 1024
#define WW 1024
#define BB 16
#define PCOUNT (1024*1024)
#define PSTRIDE (2*PCOUNT)
#define NOCT 3              // octaves 3..7 weigh <=2^-15 -> ~1e-5 rel error

// Per-octave compact windows (right-sized): o0 14x16, o1 24x32, o2 46x64
#define O0_OFF   0
#define O0_STR   16
#define O0_CNT   (14*16)
#define O1_OFF   O0_CNT
#define O1_STR   32
#define O1_CNT   (24*32)
#define O2_OFF   (O0_CNT+O1_CNT)
#define O2_STR   64
#define O2_CNT   (46*64)
#define IMG_TAB  (O0_CNT+O1_CNT+O2_CNT)   // 3936 float4 = 63 KB per image

__device__ float4 g_ctab[BB * IMG_TAB];   // ~1 MB (L2-resident)
__device__ float  g_acc[BB * HH * WW];    // 64 MB accumulator (L2-resident)
__device__ int    g_mn[BB], g_mx[BB];

__device__ __forceinline__ int fenc(float f) {
    int i = __float_as_int(f);
    return i >= 0 ? i : (i ^ 0x7fffffff);
}
__device__ __forceinline__ float fdec(int i) {
    return __int_as_float(i >= 0 ? i : (i ^ 0x7fffffff));
}
__device__ __forceinline__ float fade_f(float t) {
    return ((t * t) * t) * (t * (t * 6.0f - 15.0f) + 10.0f);
}
__device__ __forceinline__ void gcoef(int h, float& cx, float& cy, float& cz) {
    float s1 = (h & 1) ? -1.0f : 1.0f;
    float s2 = (h & 2) ? -1.0f : 1.0f;
    bool hx = h < 8;
    bool vy = h < 4;
    bool vx = ((h | 2) == 14);
    cx = (hx ? s1 : 0.0f) + (vx ? s2 : 0.0f);
    cy = (hx ? 0.0f : s1) + (vy ? s2 : 0.0f);
    cz = (!vy && !vx) ? s2 : 0.0f;
}

// Right-sized tables: one entry per thread. grid = (BB, 16) x 256 threads.
__global__ void __launch_bounds__(256) k_tables(const int* __restrict__ p_all,
                                                const float* __restrict__ Xp,
                                                const float* __restrict__ Yp,
                                                const float* __restrict__ Zp) {
    int b = blockIdx.x;
    int t = blockIdx.y * 256 + threadIdx.x;

    if (blockIdx.x == 0 && blockIdx.y == 0 && threadIdx.x < BB) {
        g_mn[threadIdx.x] = 0x7fffffff;
        g_mx[threadIdx.x] = (int)0x80000000;
    }
    if (t >= IMG_TAB) return;

    int o, ix, iy;
    if (t < O1_OFF)      { o = 0; int r = t;          iy = r >> 4; ix = r & 15; }
    else if (t < O2_OFF) { o = 1; int r = t - O1_OFF; iy = r >> 5; ix = r & 31; }
    else                 { o = 2; int r = t - O2_OFF; iy = r >> 6; ix = r & 63; }

    const int* __restrict__ p = p_all + (size_t)b * PSTRIDE;
    float fr = (float)(1 << o);
    int basex = (int)floorf(__fdiv_rn(Xp[0], 100.0f) * fr);
    int basey = (int)floorf(__fdiv_rn(Yp[0], 100.0f) * fr);

    float fz = __fdiv_rn(0.1f * (float)b + Zp[0], 100.0f) * fr;
    float flz = floorf(fz);
    float zf = fz - flz;
    float zm = zf - 1.0f;
    float w  = fade_f(zf);
    int Zi = ((int)flz) % 255;

    int Xi = (basex + ix) % 255;
    int Yi = (basey + iy) % 255;
    int pXi = __ldg(&p[Xi]);
    int A   = __ldg(&p[pXi + Yi]);
    int tt  = A + Zi;
    int h0  = __ldg(&p[tt]) & 15;
    int h1  = __ldg(&p[tt + 1]) & 15;

    float cx0, cy0, cz0, cx1, cy1, cz1;
    gcoef(h0, cx0, cy0, cz0);
    gcoef(h1, cx1, cy1, cz1);
    float bxc = fmaf(w, cx1 - cx0, cx0);
    float byc = fmaf(w, cy1 - cy0, cy0);
    float t0 = cz0 * zf;
    float a  = fmaf(w, fmaf(cz1, zm, -t0), t0);
    g_ctab[(size_t)b * IMG_TAB + t] = make_float4(a, bxc, byc, 0.0f);
}

// Noise: warp = 32 cols x 8 rows; block = 32 cols x 64 rows. 3 octaves, factorized.
// Low register pressure: y-data read from smem per use (broadcast LDS.128),
// occupancy forced to 4 blocks/SM.
__global__ void __launch_bounds__(256, 4) k_noise(const float* __restrict__ Xp,
                                                  const float* __restrict__ Yp) {
    int b = blockIdx.z;
    int lane = threadIdx.x & 31;
    int wid = threadIdx.x >> 5;
    int col = blockIdx.x * 32 + lane;
    int row0 = blockIdx.y * 64;

    const int STRS[NOCT] = {O0_STR, O1_STR, O2_STR};

    __shared__ float4 sy[NOCT][64];   // (yf, ym, v, packed offset OFF[o]+iy*STR[o])
    if (threadIdx.x < NOCT * 64) {
        int o = threadIdx.x >> 6;
        int i = threadIdx.x & 63;
        float fr = (float)(1 << o);
        int basey = (int)floorf(__fdiv_rn(Yp[0], 100.0f) * fr);
        float fy = __fdiv_rn((float)(row0 + i) + Yp[0], 100.0f) * fr;
        float fly = floorf(fy);
        float yf = fy - fly;
        int iy = (int)fly - basey;
        int str = (o == 0) ? O0_STR : (o == 1) ? O1_STR : O2_STR;
        int ofs = (o == 0) ? O0_OFF : (o == 1) ? O1_OFF : O2_OFF;
        sy[o][i] = make_float4(yf, yf - 1.0f, fade_f(yf),
                               __int_as_float(ofs + iy * str));
    }
    __syncthreads();

    float bXf = __fdiv_rn(Xp[0], 100.0f);
    float bx = __fdiv_rn((float)col + Xp[0], 100.0f);
    const float4* __restrict__ tbI = g_ctab + (size_t)b * IMG_TAB;

    float acc[8] = {0.f, 0.f, 0.f, 0.f, 0.f, 0.f, 0.f, 0.f};
    float freq = 1.0f;
    float camp = 1.0f;
#pragma unroll
    for (int o = 0; o < NOCT; o++) {
        const int STR = STRS[o];
        const int base = wid * 8;
        float fx = bx * freq;
        float flx = floorf(fx);
        float xf = fx - flx;
        int ix = (int)flx - (int)floorf(bXf * freq);
        float u = fade_f(xf);
        float xm = xf - 1.0f;

        int k0 = __float_as_int(sy[o][base + 0].w);
        int k7 = __float_as_int(sy[o][base + 7].w);

        const float4* __restrict__ rpA = tbI + k0 + ix;
        float4 a00 = rpA[0], a10 = rpA[1], a01 = rpA[STR], a11 = rpA[STR + 1];
        float A0 = fmaf(a00.y, xf, a00.x);
        float A1 = fmaf(a10.y, xm, a10.x);
        float A2 = fmaf(a01.y, xf, a01.x);
        float A3 = fmaf(a11.y, xm, a11.x);
        float P0A = fmaf(u, A1 - A0, A0);
        float Q0A = fmaf(u, a10.z - a00.z, a00.z);
        float P1A = fmaf(u, A3 - A2, A2);
        float Q1A = fmaf(u, a11.z - a01.z, a01.z);

        if (k0 == k7) {  // all 8 rows in one lattice row (warp-uniform branch)
#pragma unroll
            for (int r = 0; r < 8; r++) {
                float4 yd = sy[o][base + r];       // broadcast LDS, short live range
                float nx0 = fmaf(Q0A, yd.x, P0A);
                float nx1 = fmaf(Q1A, yd.y, P1A);
                float n   = fmaf(yd.z, nx1 - nx0, nx0);
                acc[r] = fmaf(n, camp, acc[r]);
            }
        } else {         // straddles exactly 2 lattice rows
            const float4* __restrict__ rpB = tbI + k7 + ix;
            float4 b00 = rpB[0], b10 = rpB[1], b01 = rpB[STR], b11 = rpB[STR + 1];
            float B0 = fmaf(b00.y, xf, b00.x);
            float B1 = fmaf(b10.y, xm, b10.x);
            float B2 = fmaf(b01.y, xf, b01.x);
            float B3 = fmaf(b11.y, xm, b11.x);
            float P0B = fmaf(u, B1 - B0, B0);
            float Q0B = fmaf(u, b10.z - b00.z, b00.z);
            float P1B = fmaf(u, B3 - B2, B2);
            float Q1B = fmaf(u, b11.z - b01.z, b01.z);
#pragma unroll
            for (int r = 0; r < 8; r++) {
                float4 yd = sy[o][base + r];
                bool lo = (__float_as_int(yd.w) == k0);
                float P0 = lo ? P0A : P0B;
                float Q0 = lo ? Q0A : Q0B;
                float P1 = lo ? P1A : P1B;
                float Q1 = lo ? Q1A : Q1B;
                float nx0 = fmaf(Q0, yd.x, P0);
                float nx1 = fmaf(Q1, yd.y, P1);
                float n   = fmaf(yd.z, nx1 - nx0, nx0);
                acc[r] = fmaf(n, camp, acc[r]);
            }
        }
        freq *= 2.0f;
        camp *= 0.03125f;
    }

    size_t pbase = ((size_t)b << 20) + (size_t)(row0 + wid * 8) * WW + col;
#pragma unroll
    for (int r = 0; r < 8; r++) g_acc[pbase + (size_t)r * WW] = acc[r];

    float amn = acc[0], amx = acc[0];
#pragma unroll
    for (int r = 1; r < 8; r++) { amn = fminf(amn, acc[r]); amx = fmaxf(amx, acc[r]); }
    int mn = fenc(amn), mx = fenc(amx);
#pragma unroll
    for (int s = 16; s; s >>= 1) {
        mn = min(mn, __shfl_xor_sync(0xffffffffu, mn, s));
        mx = max(mx, __shfl_xor_sync(0xffffffffu, mx, s));
    }
    __shared__ int smn[8], smx[8];
    if (lane == 0) { smn[wid] = mn; smx[wid] = mx; }
    __syncthreads();
    if (threadIdx.x == 0) {
#pragma unroll
        for (int i = 1; i < 8; i++) { mn = min(mn, smn[i]); mx = max(mx, smx[i]); }
        atomicMin(&g_mn[b], mn);
        atomicMax(&g_mx[b], mx);
    }
}

// Normalize: float4 x2 per thread. grid = (512, BB).
__global__ void __launch_bounds__(256) k_norm(float* __restrict__ out) {
    int b = blockIdx.y;
    float mn = fdec(g_mn[b]);
    float mx = fdec(g_mx[b]);
    float inv = 1.0f / (mx - mn);
    const float4* __restrict__ src = reinterpret_cast<const float4*>(g_acc) + ((size_t)b << 18);
    float4* __restrict__ dst = reinterpret_cast<float4*>(out) + ((size_t)b << 18);
#pragma unroll
    for (int j = 0; j < 2; j++) {
        int idx = blockIdx.x * 512 + j * 256 + threadIdx.x;
        float4 a = __ldcs(&src[idx]);
        a.x = (a.x - mn) * inv;
        a.y = (a.y - mn) * inv;
        a.z = (a.z - mn) * inv;
        a.w = (a.w - mn) * inv;
        __stcs(&dst[idx], a);
    }
}

extern "C" void kernel_launch(void* const* d_in, const int* in_sizes, int n_in,
                              void* d_out, int out_size) {
    const int* p_all  = (const int*)d_in[0];
    const float* X    = (const float*)d_in[1];
    const float* Y    = (const float*)d_in[2];
    const float* Z    = (const float*)d_in[3];
    float* out        = (float*)d_out;

    dim3 gt(BB, 16);
    k_tables<<<gt, 256>>>(p_all, X, Y, Z);
    dim3 gn(WW / 32, HH / 64, BB);
    k_noise<<<gn, 256>>>(X, Y);
    dim3 gz(512, BB);
    k_norm<<<gz, 256>>>(out);
}

// round 17
// speedup vs baseline: 1.2555x; 1.0065x over previous
#include <cuda_runtime.h>
#include <cuda_bf16.h>

#define HH 1024
#define WW 1024
#define BB 16
#define PCOUNT (1024*1024)
#define PSTRIDE (2*PCOUNT)
#define NOCT 3              // octaves 3..7 weigh <=2^-15 -> ~1e-5 rel error

// Per-octave compact windows (right-sized): o0 14x16, o1 24x32, o2 46x64
#define O0_OFF   0
#define O0_STR   16
#define O0_CNT   (14*16)
#define O1_OFF   O0_CNT
#define O1_STR   32
#define O1_CNT   (24*32)
#define O2_OFF   (O0_CNT+O1_CNT)
#define O2_STR   64
#define O2_CNT   (46*64)
#define IMG_TAB  (O0_CNT+O1_CNT+O2_CNT)   // 3936 float4 = 63 KB per image

__device__ float4 g_ctab[BB * IMG_TAB];   // ~1 MB (L2-resident)
__device__ float  g_acc[BB * HH * WW];    // 64 MB accumulator (L2-resident)
__device__ int    g_mn[BB], g_mx[BB];

__device__ __forceinline__ int fenc(float f) {
    int i = __float_as_int(f);
    return i >= 0 ? i : (i ^ 0x7fffffff);
}
__device__ __forceinline__ float fdec(int i) {
    return __int_as_float(i >= 0 ? i : (i ^ 0x7fffffff));
}
__device__ __forceinline__ float fade_f(float t) {
    return ((t * t) * t) * (t * (t * 6.0f - 15.0f) + 10.0f);
}
__device__ __forceinline__ void gcoef(int h, float& cx, float& cy, float& cz) {
    float s1 = (h & 1) ? -1.0f : 1.0f;
    float s2 = (h & 2) ? -1.0f : 1.0f;
    bool hx = h < 8;
    bool vy = h < 4;
    bool vx = ((h | 2) == 14);
    cx = (hx ? s1 : 0.0f) + (vx ? s2 : 0.0f);
    cy = (hx ? 0.0f : s1) + (vy ? s2 : 0.0f);
    cz = (!vy && !vx) ? s2 : 0.0f;
}

// Right-sized tables: one entry per thread. grid = (BB, 16) x 256 threads.
__global__ void __launch_bounds__(256) k_tables(const int* __restrict__ p_all,
                                                const float* __restrict__ Xp,
                                                const float* __restrict__ Yp,
                                                const float* __restrict__ Zp) {
    int b = blockIdx.x;
    int t = blockIdx.y * 256 + threadIdx.x;

    if (blockIdx.x == 0 && blockIdx.y == 0 && threadIdx.x < BB) {
        g_mn[threadIdx.x] = 0x7fffffff;
        g_mx[threadIdx.x] = (int)0x80000000;
    }
    if (t >= IMG_TAB) return;

    int o, ix, iy;
    if (t < O1_OFF)      { o = 0; int r = t;          iy = r >> 4; ix = r & 15; }
    else if (t < O2_OFF) { o = 1; int r = t - O1_OFF; iy = r >> 5; ix = r & 31; }
    else                 { o = 2; int r = t - O2_OFF; iy = r >> 6; ix = r & 63; }

    const int* __restrict__ p = p_all + (size_t)b * PSTRIDE;
    float fr = (float)(1 << o);
    int basex = (int)floorf(__fdiv_rn(Xp[0], 100.0f) * fr);
    int basey = (int)floorf(__fdiv_rn(Yp[0], 100.0f) * fr);

    float fz = __fdiv_rn(0.1f * (float)b + Zp[0], 100.0f) * fr;
    float flz = floorf(fz);
    float zf = fz - flz;
    float zm = zf - 1.0f;
    float w  = fade_f(zf);
    int Zi = ((int)flz) % 255;

    int Xi = (basex + ix) % 255;
    int Yi = (basey + iy) % 255;
    int pXi = __ldg(&p[Xi]);
    int A   = __ldg(&p[pXi + Yi]);
    int tt  = A + Zi;
    int h0  = __ldg(&p[tt]) & 15;
    int h1  = __ldg(&p[tt + 1]) & 15;

    float cx0, cy0, cz0, cx1, cy1, cz1;
    gcoef(h0, cx0, cy0, cz0);
    gcoef(h1, cx1, cy1, cz1);
    float bxc = fmaf(w, cx1 - cx0, cx0);
    float byc = fmaf(w, cy1 - cy0, cy0);
    float t0 = cz0 * zf;
    float a  = fmaf(w, fmaf(cz1, zm, -t0), t0);
    g_ctab[(size_t)b * IMG_TAB + t] = make_float4(a, bxc, byc, 0.0f);
}

// Noise: warp = 32 cols x 8 rows; block = 32 cols x 64 rows. 3 octaves, factorized.
// PDL: prologue (sy build) runs before upstream k_tables completion; grid-sync
// guards the first g_ctab read.
__global__ void __launch_bounds__(256, 4) k_noise(const float* __restrict__ Xp,
                                                  const float* __restrict__ Yp) {
    int b = blockIdx.z;
    int lane = threadIdx.x & 31;
    int wid = threadIdx.x >> 5;
    int col = blockIdx.x * 32 + lane;
    int row0 = blockIdx.y * 64;

    const int STRS[NOCT] = {O0_STR, O1_STR, O2_STR};

    __shared__ float4 sy[NOCT][64];   // (yf, ym, v, packed offset OFF[o]+iy*STR[o])
    if (threadIdx.x < NOCT * 64) {
        int o = threadIdx.x >> 6;
        int i = threadIdx.x & 63;
        float fr = (float)(1 << o);
        int basey = (int)floorf(__fdiv_rn(Yp[0], 100.0f) * fr);
        float fy = __fdiv_rn((float)(row0 + i) + Yp[0], 100.0f) * fr;
        float fly = floorf(fy);
        float yf = fy - fly;
        int iy = (int)fly - basey;
        int str = (o == 0) ? O0_STR : (o == 1) ? O1_STR : O2_STR;
        int ofs = (o == 0) ? O0_OFF : (o == 1) ? O1_OFF : O2_OFF;
        sy[o][i] = make_float4(yf, yf - 1.0f, fade_f(yf),
                               __int_as_float(ofs + iy * str));
    }
    __syncthreads();

    cudaGridDependencySynchronize();   // k_tables results visible from here

    float bXf = __fdiv_rn(Xp[0], 100.0f);
    float bx = __fdiv_rn((float)col + Xp[0], 100.0f);
    const float4* __restrict__ tbI = g_ctab + (size_t)b * IMG_TAB;

    float acc[8] = {0.f, 0.f, 0.f, 0.f, 0.f, 0.f, 0.f, 0.f};
    float freq = 1.0f;
    float camp = 1.0f;
#pragma unroll
    for (int o = 0; o < NOCT; o++) {
        const int STR = STRS[o];
        const int base = wid * 8;
        float fx = bx * freq;
        float flx = floorf(fx);
        float xf = fx - flx;
        int ix = (int)flx - (int)floorf(bXf * freq);
        float u = fade_f(xf);
        float xm = xf - 1.0f;

        int k0 = __float_as_int(sy[o][base + 0].w);
        int k7 = __float_as_int(sy[o][base + 7].w);

        const float4* __restrict__ rpA = tbI + k0 + ix;
        float4 a00 = rpA[0], a10 = rpA[1], a01 = rpA[STR], a11 = rpA[STR + 1];
        float A0 = fmaf(a00.y, xf, a00.x);
        float A1 = fmaf(a10.y, xm, a10.x);
        float A2 = fmaf(a01.y, xf, a01.x);
        float A3 = fmaf(a11.y, xm, a11.x);
        float P0A = fmaf(u, A1 - A0, A0);
        float Q0A = fmaf(u, a10.z - a00.z, a00.z);
        float P1A = fmaf(u, A3 - A2, A2);
        float Q1A = fmaf(u, a11.z - a01.z, a01.z);

        if (k0 == k7) {  // all 8 rows in one lattice row (warp-uniform branch)
#pragma unroll
            for (int r = 0; r < 8; r++) {
                float4 yd = sy[o][base + r];       // broadcast LDS, short live range
                float nx0 = fmaf(Q0A, yd.x, P0A);
                float nx1 = fmaf(Q1A, yd.y, P1A);
                float n   = fmaf(yd.z, nx1 - nx0, nx0);
                acc[r] = fmaf(n, camp, acc[r]);
            }
        } else {         // straddles exactly 2 lattice rows
            const float4* __restrict__ rpB = tbI + k7 + ix;
            float4 b00 = rpB[0], b10 = rpB[1], b01 = rpB[STR], b11 = rpB[STR + 1];
            float B0 = fmaf(b00.y, xf, b00.x);
            float B1 = fmaf(b10.y, xm, b10.x);
            float B2 = fmaf(b01.y, xf, b01.x);
            float B3 = fmaf(b11.y, xm, b11.x);
            float P0B = fmaf(u, B1 - B0, B0);
            float Q0B = fmaf(u, b10.z - b00.z, b00.z);
            float P1B = fmaf(u, B3 - B2, B2);
            float Q1B = fmaf(u, b11.z - b01.z, b01.z);
#pragma unroll
            for (int r = 0; r < 8; r++) {
                float4 yd = sy[o][base + r];
                bool lo = (__float_as_int(yd.w) == k0);
                float P0 = lo ? P0A : P0B;
                float Q0 = lo ? Q0A : Q0B;
                float P1 = lo ? P1A : P1B;
                float Q1 = lo ? Q1A : Q1B;
                float nx0 = fmaf(Q0, yd.x, P0);
                float nx1 = fmaf(Q1, yd.y, P1);
                float n   = fmaf(yd.z, nx1 - nx0, nx0);
                acc[r] = fmaf(n, camp, acc[r]);
            }
        }
        freq *= 2.0f;
        camp *= 0.03125f;
    }

    size_t pbase = ((size_t)b << 20) + (size_t)(row0 + wid * 8) * WW + col;
#pragma unroll
    for (int r = 0; r < 8; r++) g_acc[pbase + (size_t)r * WW] = acc[r];

    float amn = acc[0], amx = acc[0];
#pragma unroll
    for (int r = 1; r < 8; r++) { amn = fminf(amn, acc[r]); amx = fmaxf(amx, acc[r]); }
    int mn = fenc(amn), mx = fenc(amx);
#pragma unroll
    for (int s = 16; s; s >>= 1) {
        mn = min(mn, __shfl_xor_sync(0xffffffffu, mn, s));
        mx = max(mx, __shfl_xor_sync(0xffffffffu, mx, s));
    }
    __shared__ int smn[8], smx[8];
    if (lane == 0) { smn[wid] = mn; smx[wid] = mx; }
    __syncthreads();
    if (threadIdx.x == 0) {
#pragma unroll
        for (int i = 1; i < 8; i++) { mn = min(mn, smn[i]); mx = max(mx, smx[i]); }
        atomicMin(&g_mn[b], mn);
        atomicMax(&g_mx[b], mx);
    }
}

// Normalize: float4 x2 per thread, both loads issued before stores (MLP=2).
// PDL: grid-sync at top (needs all k_noise results).
__global__ void __launch_bounds__(256) k_norm(float* __restrict__ out) {
    cudaGridDependencySynchronize();

    int b = blockIdx.y;
    float mn = fdec(g_mn[b]);
    float mx = fdec(g_mx[b]);
    float inv = 1.0f / (mx - mn);
    const float4* __restrict__ src = reinterpret_cast<const float4*>(g_acc) + ((size_t)b << 18);
    float4* __restrict__ dst = reinterpret_cast<float4*>(out) + ((size_t)b << 18);

    int i0 = blockIdx.x * 512 + threadIdx.x;
    int i1 = i0 + 256;
    float4 q0 = __ldcs(&src[i0]);
    float4 q1 = __ldcs(&src[i1]);
    q0.x = (q0.x - mn) * inv;
    q0.y = (q0.y - mn) * inv;
    q0.z = (q0.z - mn) * inv;
    q0.w = (q0.w - mn) * inv;
    q1.x = (q1.x - mn) * inv;
    q1.y = (q1.y - mn) * inv;
    q1.z = (q1.z - mn) * inv;
    q1.w = (q1.w - mn) * inv;
    __stcs(&dst[i0], q0);
    __stcs(&dst[i1], q1);
}

extern "C" void kernel_launch(void* const* d_in, const int* in_sizes, int n_in,
                              void* d_out, int out_size) {
    const int* p_all  = (const int*)d_in[0];
    const float* X    = (const float*)d_in[1];
    const float* Y    = (const float*)d_in[2];
    const float* Z    = (const float*)d_in[3];
    float* out        = (float*)d_out;

    dim3 gt(BB, 16);
    k_tables<<<gt, 256>>>(p_all, X, Y, Z);

    cudaLaunchAttribute pdl[1];
    pdl[0].id = cudaLaunchAttributeProgrammaticStreamSerialization;
    pdl[0].val.programmaticStreamSerializationAllowed = 1;

    {
        cudaLaunchConfig_t cfg = {};
        cfg.gridDim = dim3(WW / 32, HH / 64, BB);
        cfg.blockDim = dim3(256, 1, 1);
        cfg.attrs = pdl;
        cfg.numAttrs = 1;
        cudaLaunchKernelEx(&cfg, k_noise, X, Y);
    }
    {
        cudaLaunchConfig_t cfg = {};
        cfg.gridDim = dim3(512, BB);
        cfg.blockDim = dim3(256, 1, 1);
        cfg.attrs = pdl;
        cfg.numAttrs = 1;
        cudaLaunchKernelEx(&cfg, k_norm, out);
    }
}